// round 1
// baseline (speedup 1.0000x reference)
#include <cuda_runtime.h>
#include <math.h>

#define BATCH  64
#define NSITES 256
#define HD     128
#define OUTC   10

// Static scratch (no cudaMalloc allowed):
//  bufA holds up to 128 matrices/batch (level-0 output), bufB up to 64.
__device__ float g_bufA[(size_t)BATCH * 128 * HD * HD];  // 536 MB
__device__ float g_bufB[(size_t)BATCH * 64  * HD * HD];  // 268 MB
__device__ float g_lognorm[BATCH * 256];                 // 255 used/batch

// ---------------------------------------------------------------------------
// Shared matmul core: C(128x128) = A(128x128) @ B(128x128), Frobenius-normalize,
// log(norm) recorded. 256 threads: 16x16 grid, 8x8 microtile each, k-tiles of 16.
// As is stored transposed: As[kk][l] so the inner loop reads are contiguous.
// ---------------------------------------------------------------------------

__device__ __forceinline__ void mm_epilogue(
    float acc[8][8], float* red, int tid, int tx, int ty,
    float* __restrict__ outp, int b, int lslot)
{
    float s = 0.f;
    #pragma unroll
    for (int i = 0; i < 8; ++i)
        #pragma unroll
        for (int jj = 0; jj < 8; ++jj)
            s = fmaf(acc[i][jj], acc[i][jj], s);
    red[tid] = s;
    __syncthreads();
    for (int st = 128; st > 0; st >>= 1) {
        if (tid < st) red[tid] += red[tid + st];
        __syncthreads();
    }
    float nrm = fmaxf(sqrtf(red[0]), 1e-12f);
    if (tid == 0) g_lognorm[b * 256 + lslot] = logf(nrm);
    float inv = 1.f / nrm;
    #pragma unroll
    for (int i = 0; i < 8; ++i) {
        float4 v0, v1;
        v0.x = acc[i][0] * inv; v0.y = acc[i][1] * inv;
        v0.z = acc[i][2] * inv; v0.w = acc[i][3] * inv;
        v1.x = acc[i][4] * inv; v1.y = acc[i][5] * inv;
        v1.z = acc[i][6] * inv; v1.w = acc[i][7] * inv;
        float* row = outp + (size_t)(ty * 8 + i) * HD + tx * 8;
        *(float4*)(row)     = v0;
        *(float4*)(row + 4) = v1;
    }
}

__device__ __forceinline__ void mm_inner(
    float acc[8][8], const float (*As)[132], const float (*Bs)[132], int tx, int ty)
{
    #pragma unroll
    for (int kk = 0; kk < 16; ++kk) {
        float a[8], bb[8];
        *(float4*)(a)      = *(const float4*)(&As[kk][ty * 8]);
        *(float4*)(a + 4)  = *(const float4*)(&As[kk][ty * 8 + 4]);
        *(float4*)(bb)     = *(const float4*)(&Bs[kk][tx * 8]);
        *(float4*)(bb + 4) = *(const float4*)(&Bs[kk][tx * 8 + 4]);
        #pragma unroll
        for (int i = 0; i < 8; ++i)
            #pragma unroll
            for (int jj = 0; jj < 8; ++jj)
                acc[i][jj] = fmaf(a[i], bb[jj], acc[i][jj]);
    }
}

// ---------------------------------------------------------------------------
// Level 0: items generated on the fly from cores/core0/x.
// Item k (k>=1): M[l][h] = (1-x[b,k])*cores[k-1,l,0,h] + x[b,k]*cores[k-1,l,1,h]
// Item 0:        row 0 = (1-x[b,0])*core0[0,:] + x[b,0]*core0[1,:], rest zero
// ---------------------------------------------------------------------------
__global__ void __launch_bounds__(256, 2) mps_level0(
    const float* __restrict__ x, const float* __restrict__ core0,
    const float* __restrict__ cores)
{
    const int j   = blockIdx.x;   // pair 0..127
    const int b   = blockIdx.y;
    const int tid = threadIdx.x;
    const int tx  = tid & 15;
    const int ty  = tid >> 4;

    __shared__ float As[16][132];
    __shared__ float Bs[16][132];
    __shared__ float red[256];

    const int kA = 2 * j;
    const int kB = 2 * j + 1;
    const float xA = x[b * NSITES + kA];
    const float xB = x[b * NSITES + kB];
    const float wA0 = 1.f - xA, wA1 = xA;
    const float wB0 = 1.f - xB, wB1 = xB;
    const float* coresA = cores + (size_t)(kA - 1) * (HD * 2 * HD); // valid kA>=1
    const float* coresB = cores + (size_t)(kB - 1) * (HD * 2 * HD);

    float acc[8][8];
    #pragma unroll
    for (int i = 0; i < 8; ++i)
        #pragma unroll
        for (int jj = 0; jj < 8; ++jj) acc[i][jj] = 0.f;

    const int lA  = tid >> 1;         // A-tile: row this thread loads
    const int kkA = (tid & 1) * 8;    // A-tile: first of 8 k-cols
    const int kkB = tid >> 4;         // B-tile: k-row
    const int hB  = (tid & 15) * 8;   // B-tile: first of 8 h-cols

    for (int kt = 0; kt < 8; ++kt) {
        // ---- load A tile (transposed into As[kk][l]) ----
        if (kA == 0) {
            if (lA == 0) {
                #pragma unroll
                for (int i = 0; i < 8; ++i) {
                    int c = kt * 16 + kkA + i;
                    As[kkA + i][0] = wA0 * core0[c] + wA1 * core0[HD + c];
                }
            } else {
                #pragma unroll
                for (int i = 0; i < 8; ++i) As[kkA + i][lA] = 0.f;
            }
        } else {
            const float* p0 = coresA + ((size_t)lA * 2) * HD + kt * 16 + kkA;
            float4 a0 = *(const float4*)(p0);
            float4 a1 = *(const float4*)(p0 + 4);
            float4 c0 = *(const float4*)(p0 + HD);
            float4 c1 = *(const float4*)(p0 + HD + 4);
            As[kkA + 0][lA] = wA0 * a0.x + wA1 * c0.x;
            As[kkA + 1][lA] = wA0 * a0.y + wA1 * c0.y;
            As[kkA + 2][lA] = wA0 * a0.z + wA1 * c0.z;
            As[kkA + 3][lA] = wA0 * a0.w + wA1 * c0.w;
            As[kkA + 4][lA] = wA0 * a1.x + wA1 * c1.x;
            As[kkA + 5][lA] = wA0 * a1.y + wA1 * c1.y;
            As[kkA + 6][lA] = wA0 * a1.z + wA1 * c1.z;
            As[kkA + 7][lA] = wA0 * a1.w + wA1 * c1.w;
        }
        // ---- load B tile ----
        {
            int r = kt * 16 + kkB;
            const float* p0 = coresB + ((size_t)r * 2) * HD + hB;
            float4 a0 = *(const float4*)(p0);
            float4 a1 = *(const float4*)(p0 + 4);
            float4 c0 = *(const float4*)(p0 + HD);
            float4 c1 = *(const float4*)(p0 + HD + 4);
            float4 w0, w1;
            w0.x = wB0 * a0.x + wB1 * c0.x; w0.y = wB0 * a0.y + wB1 * c0.y;
            w0.z = wB0 * a0.z + wB1 * c0.z; w0.w = wB0 * a0.w + wB1 * c0.w;
            w1.x = wB0 * a1.x + wB1 * c1.x; w1.y = wB0 * a1.y + wB1 * c1.y;
            w1.z = wB0 * a1.z + wB1 * c1.z; w1.w = wB0 * a1.w + wB1 * c1.w;
            *(float4*)(&Bs[kkB][hB])     = w0;
            *(float4*)(&Bs[kkB][hB + 4]) = w1;
        }
        __syncthreads();
        mm_inner(acc, As, Bs, tx, ty);
        __syncthreads();
    }

    float* outp = g_bufA + ((size_t)b * 128 + j) * (HD * HD);
    mm_epilogue(acc, red, tid, tx, ty, outp, b, /*lslot=*/j);
}

// ---------------------------------------------------------------------------
// Generic level: reads pairs of matrices from one ping-pong buffer, writes the
// normalized product to the other. pairs = gridDim.x; in batch stride = 2*pairs.
// ---------------------------------------------------------------------------
template <bool A2B>
__global__ void __launch_bounds__(256, 2) mps_level(int lbase)
{
    const int j     = blockIdx.x;
    const int b     = blockIdx.y;
    const int pairs = gridDim.x;
    const int tid   = threadIdx.x;
    const int tx    = tid & 15;
    const int ty    = tid >> 4;

    __shared__ float As[16][132];
    __shared__ float Bs[16][132];
    __shared__ float red[256];

    const float* in  = A2B ? g_bufA : g_bufB;
    float*       out = A2B ? g_bufB : g_bufA;

    const float* Ain = in + ((size_t)b * pairs * 2 + 2 * j) * (HD * HD);
    const float* Bin = Ain + HD * HD;

    float acc[8][8];
    #pragma unroll
    for (int i = 0; i < 8; ++i)
        #pragma unroll
        for (int jj = 0; jj < 8; ++jj) acc[i][jj] = 0.f;

    const int lA  = tid >> 1;
    const int kkA = (tid & 1) * 8;
    const int kkB = tid >> 4;
    const int hB  = (tid & 15) * 8;

    for (int kt = 0; kt < 8; ++kt) {
        {
            const float* p = Ain + (size_t)lA * HD + kt * 16 + kkA;
            float4 a0 = *(const float4*)(p);
            float4 a1 = *(const float4*)(p + 4);
            As[kkA + 0][lA] = a0.x; As[kkA + 1][lA] = a0.y;
            As[kkA + 2][lA] = a0.z; As[kkA + 3][lA] = a0.w;
            As[kkA + 4][lA] = a1.x; As[kkA + 5][lA] = a1.y;
            As[kkA + 6][lA] = a1.z; As[kkA + 7][lA] = a1.w;
        }
        {
            int r = kt * 16 + kkB;
            const float* p = Bin + (size_t)r * HD + hB;
            *(float4*)(&Bs[kkB][hB])     = *(const float4*)(p);
            *(float4*)(&Bs[kkB][hB + 4]) = *(const float4*)(p + 4);
        }
        __syncthreads();
        mm_inner(acc, As, Bs, tx, ty);
        __syncthreads();
    }

    float* outp = out + ((size_t)b * pairs + j) * (HD * HD);
    mm_epilogue(acc, red, tid, tx, ty, outp, b, lbase + j);
}

// ---------------------------------------------------------------------------
// Final: logits[b,o] = <row0(final), classifier[o,:]> + sum(lognorms[b])
// Final matrix lives in g_bufB (last level is A2B).
// ---------------------------------------------------------------------------
__global__ void __launch_bounds__(128) mps_final(
    const float* __restrict__ classifier, float* __restrict__ out)
{
    const int b   = blockIdx.x;
    const int tid = threadIdx.x;
    __shared__ float red[128];
    __shared__ float v[HD];

    float ls = 0.f;
    for (int i = tid; i < 255; i += 128) ls += g_lognorm[b * 256 + i];
    red[tid] = ls;
    v[tid]   = g_bufB[(size_t)b * HD * HD + tid];  // row 0 of final matrix
    __syncthreads();
    for (int st = 64; st > 0; st >>= 1) {
        if (tid < st) red[tid] += red[tid + st];
        __syncthreads();
    }
    float lsum = red[0];
    if (tid < OUTC) {
        float s = 0.f;
        #pragma unroll
        for (int h = 0; h < HD; ++h)
            s = fmaf(v[h], classifier[tid * HD + h], s);
        out[b * OUTC + tid] = s + lsum;
    }
}

extern "C" void kernel_launch(void* const* d_in, const int* in_sizes, int n_in,
                              void* d_out, int out_size)
{
    (void)in_sizes; (void)n_in; (void)out_size;
    const float* x          = (const float*)d_in[0];
    const float* core0      = (const float*)d_in[1];
    const float* cores      = (const float*)d_in[2];
    const float* classifier = (const float*)d_in[3];
    float*       out        = (float*)d_out;

    dim3 blk(256);
    mps_level0<<<dim3(128, BATCH), blk>>>(x, core0, cores);   // 256 -> 128 (A)
    mps_level<true ><<<dim3(64, BATCH), blk>>>(128);          // A -> B
    mps_level<false><<<dim3(32, BATCH), blk>>>(192);          // B -> A
    mps_level<true ><<<dim3(16, BATCH), blk>>>(224);          // A -> B
    mps_level<false><<<dim3( 8, BATCH), blk>>>(240);          // B -> A
    mps_level<true ><<<dim3( 4, BATCH), blk>>>(248);          // A -> B
    mps_level<false><<<dim3( 2, BATCH), blk>>>(252);          // B -> A
    mps_level<true ><<<dim3( 1, BATCH), blk>>>(254);          // A -> B (final in B)
    mps_final<<<BATCH, 128>>>(classifier, out);
}

// round 3
// speedup vs baseline: 3.6198x; 3.6198x over previous
#include <cuda_runtime.h>
#include <cuda_bf16.h>
#include <math.h>
#include <stdint.h>

#define BATCH  64
#define HD     128
#define OUTC   10
#define PITCH  136          // padded row pitch in bf16 elems (conflict-free ldmatrix)

// ---------------- static scratch (bf16 intermediates) ----------------
__device__ __nv_bfloat16 g_bufA[(size_t)BATCH * 128 * HD * HD]; // 268 MB
__device__ __nv_bfloat16 g_bufB[(size_t)BATCH * 64  * HD * HD]; // 134 MB
__device__ float g_lognorm[BATCH * 256];

// ---------------- helpers ----------------
__device__ __forceinline__ uint32_t smem_u32(const void* p) {
    uint32_t a;
    asm("{ .reg .u64 t; cvta.to.shared.u64 t, %1; cvt.u32.u64 %0, t; }" : "=r"(a) : "l"(p));
    return a;
}

__device__ __forceinline__ void ldm_x4(uint32_t* r, uint32_t addr) {
    asm volatile("ldmatrix.sync.aligned.m8n8.x4.shared.b16 {%0,%1,%2,%3}, [%4];"
                 : "=r"(r[0]), "=r"(r[1]), "=r"(r[2]), "=r"(r[3]) : "r"(addr));
}
__device__ __forceinline__ void ldm_x4_t(uint32_t* r, uint32_t addr) {
    asm volatile("ldmatrix.sync.aligned.m8n8.x4.trans.shared.b16 {%0,%1,%2,%3}, [%4];"
                 : "=r"(r[0]), "=r"(r[1]), "=r"(r[2]), "=r"(r[3]) : "r"(addr));
}
__device__ __forceinline__ void mma16816(float* c, const uint32_t* a, const uint32_t* b) {
    asm volatile(
        "mma.sync.aligned.m16n8k16.row.col.f32.bf16.bf16.f32 "
        "{%0,%1,%2,%3}, {%4,%5,%6,%7}, {%8,%9}, {%0,%1,%2,%3};"
        : "+f"(c[0]), "+f"(c[1]), "+f"(c[2]), "+f"(c[3])
        : "r"(a[0]), "r"(a[1]), "r"(a[2]), "r"(a[3]), "r"(b[0]), "r"(b[1]));
}

__device__ __forceinline__ uint32_t packbf2(float a, float b) {
    __nv_bfloat162 t = __floats2bfloat162_rn(a, b);
    return *reinterpret_cast<uint32_t*>(&t);
}

__device__ __forceinline__ uint4 blend8(const float* p, float w0, float w1) {
    float4 a0 = *(const float4*)(p);
    float4 a1 = *(const float4*)(p + 4);
    float4 b0 = *(const float4*)(p + HD);
    float4 b1 = *(const float4*)(p + HD + 4);
    uint4 r;
    r.x = packbf2(w0 * a0.x + w1 * b0.x, w0 * a0.y + w1 * b0.y);
    r.y = packbf2(w0 * a0.z + w1 * b0.z, w0 * a0.w + w1 * b0.w);
    r.z = packbf2(w0 * a1.x + w1 * b1.x, w0 * a1.y + w1 * b1.y);
    r.w = packbf2(w0 * a1.z + w1 * b1.z, w0 * a1.w + w1 * b1.w);
    return r;
}

// ---------------- SMEM layout ----------------
#define TILE_ELEMS (HD * PITCH)                 // 17408 elems, 34816 B
#define SM_AS      0
#define SM_BS      (TILE_ELEMS * 2)             // bytes
#define SM_RED     (TILE_ELEMS * 4)             // 8 floats
#define SMEM_BYTES (SM_RED + 64)

// ---------------------------------------------------------------------------
// Shared MMA + norm epilogue. As/Bs already populated (row-major, pitch 136).
// C = As(128x128) @ Bs(128x128); Frobenius-normalize; bf16 row-major out.
// ---------------------------------------------------------------------------
__device__ __forceinline__ void mma_core(char* sm, uint32_t smb,
                                         __nv_bfloat16* __restrict__ outp,
                                         float* __restrict__ ln_slot) {
    const int tid  = threadIdx.x;
    const int lane = tid & 31, wid = tid >> 5;
    const int wr = wid >> 2, wc = wid & 3;      // warp tile: rows wr*64, cols wc*32

    float acc[4][4][4];
    #pragma unroll
    for (int i = 0; i < 4; ++i)
        #pragma unroll
        for (int j = 0; j < 4; ++j)
            #pragma unroll
            for (int v = 0; v < 4; ++v) acc[i][j][v] = 0.f;

    const uint32_t a_base = smb + SM_AS;
    const uint32_t b_base = smb + SM_BS;
    const int l15 = lane & 15, lhi = (lane >> 4) << 3;

    #pragma unroll
    for (int kc = 0; kc < 8; ++kc) {
        const int k0 = kc * 16;
        uint32_t a[4][4], bf[2][4];
        #pragma unroll
        for (int mi = 0; mi < 4; ++mi) {
            int row = wr * 64 + mi * 16 + l15;
            ldm_x4(a[mi], a_base + (uint32_t)(row * PITCH + k0 + lhi) * 2);
        }
        #pragma unroll
        for (int nb = 0; nb < 2; ++nb) {
            int krow = k0 + l15;
            int ncol = wc * 32 + nb * 16 + lhi;
            ldm_x4_t(bf[nb], b_base + (uint32_t)(krow * PITCH + ncol) * 2);
        }
        #pragma unroll
        for (int mi = 0; mi < 4; ++mi)
            #pragma unroll
            for (int nj = 0; nj < 4; ++nj)
                mma16816(acc[mi][nj], a[mi], &bf[nj >> 1][(nj & 1) * 2]);
    }

    // Frobenius norm
    float s = 0.f;
    #pragma unroll
    for (int i = 0; i < 4; ++i)
        #pragma unroll
        for (int j = 0; j < 4; ++j)
            #pragma unroll
            for (int v = 0; v < 4; ++v) s = fmaf(acc[i][j][v], acc[i][j][v], s);
    #pragma unroll
    for (int o = 16; o > 0; o >>= 1) s += __shfl_xor_sync(0xffffffffu, s, o);

    float* red = (float*)(sm + SM_RED);
    if (lane == 0) red[wid] = s;
    __syncthreads();
    if (tid == 0) {
        float t = 0.f;
        #pragma unroll
        for (int w = 0; w < 8; ++w) t += red[w];
        float nrm = fmaxf(sqrtf(t), 1e-12f);
        *ln_slot = logf(nrm);
        red[0] = 1.f / nrm;
    }
    __syncthreads();
    const float inv = red[0];

    // Normalize + store bf16 row-major (packed bf16x2 per 2 cols)
    const int g = lane >> 2, q = lane & 3;
    #pragma unroll
    for (int mi = 0; mi < 4; ++mi) {
        int r0 = wr * 64 + mi * 16 + g;
        #pragma unroll
        for (int nj = 0; nj < 4; ++nj) {
            int c = wc * 32 + nj * 8 + q * 2;
            *(uint32_t*)((char*)outp + (size_t)r0 * 256 + c * 2) =
                packbf2(acc[mi][nj][0] * inv, acc[mi][nj][1] * inv);
            *(uint32_t*)((char*)outp + (size_t)(r0 + 8) * 256 + c * 2) =
                packbf2(acc[mi][nj][2] * inv, acc[mi][nj][3] * inv);
        }
    }
}

// Copy global row-major bf16 [128][128] -> padded SMEM tile.
__device__ __forceinline__ void load_tile(char* sm, int off_bytes,
                                          const __nv_bfloat16* src, int tid) {
    #pragma unroll
    for (int it = 0; it < 8; ++it) {
        int idx = it * 256 + tid;
        int row = idx >> 4, col = (idx & 15) << 3;
        uint4 v = *(const uint4*)(src + (size_t)row * HD + col);
        *(uint4*)(sm + off_bytes + (size_t)(row * PITCH + col) * 2) = v;
    }
}

// ---------------- Level 0: items built from cores/core0/x ----------------
__global__ void __launch_bounds__(256) mps_level0(
    const float* __restrict__ x, const float* __restrict__ core0,
    const float* __restrict__ cores)
{
    extern __shared__ char sm[];
    const int j = blockIdx.x, b = blockIdx.y, tid = threadIdx.x;
    uint32_t smb = smem_u32(sm);

    const int kA = 2 * j, kB = 2 * j + 1;
    const float xA = x[b * 256 + kA], xB = x[b * 256 + kB];
    const float wA0 = 1.f - xA, wA1 = xA;
    const float wB0 = 1.f - xB, wB1 = xB;
    const float* cA = cores + (size_t)(kA - 1) * (HD * 2 * HD);
    const float* cB = cores + (size_t)(kB - 1) * (HD * 2 * HD);

    #pragma unroll
    for (int it = 0; it < 8; ++it) {
        int idx = it * 256 + tid;
        int l = idx >> 4, h = (idx & 15) << 3;
        uint4 vA;
        if (kA == 0) {
            if (l == 0) {
                vA.x = packbf2(wA0*core0[h+0]+wA1*core0[HD+h+0], wA0*core0[h+1]+wA1*core0[HD+h+1]);
                vA.y = packbf2(wA0*core0[h+2]+wA1*core0[HD+h+2], wA0*core0[h+3]+wA1*core0[HD+h+3]);
                vA.z = packbf2(wA0*core0[h+4]+wA1*core0[HD+h+4], wA0*core0[h+5]+wA1*core0[HD+h+5]);
                vA.w = packbf2(wA0*core0[h+6]+wA1*core0[HD+h+6], wA0*core0[h+7]+wA1*core0[HD+h+7]);
            } else {
                vA = make_uint4(0, 0, 0, 0);
            }
        } else {
            vA = blend8(cA + ((size_t)l * 2) * HD + h, wA0, wA1);
        }
        *(uint4*)(sm + SM_AS + (size_t)(l * PITCH + h) * 2) = vA;

        uint4 vB = blend8(cB + ((size_t)l * 2) * HD + h, wB0, wB1);
        *(uint4*)(sm + SM_BS + (size_t)(l * PITCH + h) * 2) = vB;
    }
    __syncthreads();

    __nv_bfloat16* outp = g_bufA + ((size_t)b * 128 + j) * (HD * HD);
    mma_core(sm, smb, outp, &g_lognorm[b * 256 + j]);
}

// ---------------- Generic level ----------------
template <bool A2B>
__global__ void __launch_bounds__(256) mps_level(int lbase)
{
    extern __shared__ char sm[];
    const int j = blockIdx.x, b = blockIdx.y, pairs = gridDim.x;
    const int tid = threadIdx.x;
    uint32_t smb = smem_u32(sm);

    const __nv_bfloat16* in  = A2B ? g_bufA : g_bufB;
    __nv_bfloat16*       out = A2B ? g_bufB : g_bufA;
    const __nv_bfloat16* L = in + ((size_t)b * pairs * 2 + 2 * j) * (HD * HD);
    const __nv_bfloat16* R = L + HD * HD;

    load_tile(sm, SM_AS, L, tid);
    load_tile(sm, SM_BS, R, tid);
    __syncthreads();

    __nv_bfloat16* outp = out + ((size_t)b * pairs + j) * (HD * HD);
    mma_core(sm, smb, outp, &g_lognorm[b * 256 + lbase + j]);
}

// ---------------- Final: logits ----------------
__global__ void __launch_bounds__(128) mps_final(
    const float* __restrict__ classifier, float* __restrict__ out)
{
    const int b = blockIdx.x, tid = threadIdx.x;
    __shared__ float red[128];
    __shared__ float v[HD];

    float ls = 0.f;
    for (int i = tid; i < 255; i += 128) ls += g_lognorm[b * 256 + i];
    red[tid] = ls;
    v[tid] = __bfloat162float(g_bufB[(size_t)b * HD * HD + tid]);  // row 0 of final matrix
    __syncthreads();
    for (int st = 64; st > 0; st >>= 1) {
        if (tid < st) red[tid] += red[tid + st];
        __syncthreads();
    }
    float lsum = red[0];
    if (tid < OUTC) {
        float s = 0.f;
        #pragma unroll
        for (int h = 0; h < HD; ++h)
            s = fmaf(v[h], classifier[tid * HD + h], s);
        out[b * OUTC + tid] = s + lsum;
    }
}

extern "C" void kernel_launch(void* const* d_in, const int* in_sizes, int n_in,
                              void* d_out, int out_size)
{
    (void)in_sizes; (void)n_in; (void)out_size;
    const float* x          = (const float*)d_in[0];
    const float* core0      = (const float*)d_in[1];
    const float* cores      = (const float*)d_in[2];
    const float* classifier = (const float*)d_in[3];
    float*       out        = (float*)d_out;

    cudaFuncSetAttribute(mps_level0, cudaFuncAttributeMaxDynamicSharedMemorySize, SMEM_BYTES);
    cudaFuncSetAttribute(mps_level<true>,  cudaFuncAttributeMaxDynamicSharedMemorySize, SMEM_BYTES);
    cudaFuncSetAttribute(mps_level<false>, cudaFuncAttributeMaxDynamicSharedMemorySize, SMEM_BYTES);

    mps_level0<<<dim3(128, BATCH), 256, SMEM_BYTES>>>(x, core0, cores); // 256 -> 128 (A)
    mps_level<true ><<<dim3(64, BATCH), 256, SMEM_BYTES>>>(128);        // A -> B
    mps_level<false><<<dim3(32, BATCH), 256, SMEM_BYTES>>>(192);        // B -> A
    mps_level<true ><<<dim3(16, BATCH), 256, SMEM_BYTES>>>(224);        // A -> B
    mps_level<false><<<dim3( 8, BATCH), 256, SMEM_BYTES>>>(240);        // B -> A
    mps_level<true ><<<dim3( 4, BATCH), 256, SMEM_BYTES>>>(248);        // A -> B
    mps_level<false><<<dim3( 2, BATCH), 256, SMEM_BYTES>>>(252);        // B -> A
    mps_level<true ><<<dim3( 1, BATCH), 256, SMEM_BYTES>>>(254);        // A -> B (final in B)
    mps_final<<<BATCH, 128>>>(classifier, out);
}

// round 4
// speedup vs baseline: 4.1633x; 1.1502x over previous
#include <cuda_runtime.h>
#include <cuda_bf16.h>
#include <math.h>
#include <stdint.h>

#define BATCH  64
#define HD     128
#define OUTC   10
#define PITCH  136                       // padded row pitch (bf16 elems)
#define TILE_B (HD * PITCH * 2)          // 34816 bytes per tile

// ---------------- static scratch ----------------
__device__ __nv_bfloat16 g_bufA[(size_t)BATCH * 128 * HD * HD]; // 268 MB
__device__ __nv_bfloat16 g_bufB[(size_t)BATCH * 64  * HD * HD]; // 134 MB
__device__ __nv_bfloat16 g_cores_bf[255 * HD * 2 * HD];         // 16.7 MB
__device__ __nv_bfloat16 g_core0_bf[2 * HD];
__device__ float g_lognorm[BATCH * 256];

// ---------------- helpers ----------------
__device__ __forceinline__ uint32_t smem_u32(const void* p) {
    uint32_t a;
    asm("{ .reg .u64 t; cvta.to.shared.u64 t, %1; cvt.u32.u64 %0, t; }" : "=r"(a) : "l"(p));
    return a;
}
__device__ __forceinline__ void ldm_x4(uint32_t* r, uint32_t addr) {
    asm volatile("ldmatrix.sync.aligned.m8n8.x4.shared.b16 {%0,%1,%2,%3}, [%4];"
                 : "=r"(r[0]), "=r"(r[1]), "=r"(r[2]), "=r"(r[3]) : "r"(addr));
}
__device__ __forceinline__ void ldm_x4_t(uint32_t* r, uint32_t addr) {
    asm volatile("ldmatrix.sync.aligned.m8n8.x4.trans.shared.b16 {%0,%1,%2,%3}, [%4];"
                 : "=r"(r[0]), "=r"(r[1]), "=r"(r[2]), "=r"(r[3]) : "r"(addr));
}
__device__ __forceinline__ void mma16816(float* c, const uint32_t* a, const uint32_t* b) {
    asm volatile(
        "mma.sync.aligned.m16n8k16.row.col.f32.bf16.bf16.f32 "
        "{%0,%1,%2,%3}, {%4,%5,%6,%7}, {%8,%9}, {%0,%1,%2,%3};"
        : "+f"(c[0]), "+f"(c[1]), "+f"(c[2]), "+f"(c[3])
        : "r"(a[0]), "r"(a[1]), "r"(a[2]), "r"(a[3]), "r"(b[0]), "r"(b[1]));
}
__device__ __forceinline__ uint32_t packbf2(float a, float b) {
    __nv_bfloat162 t = __floats2bfloat162_rn(a, b);
    return *reinterpret_cast<uint32_t*>(&t);
}
__device__ __forceinline__ uint32_t blend2(uint32_t a, uint32_t b, float w0, float w1) {
    float2 fa = __bfloat1622float2(*reinterpret_cast<__nv_bfloat162*>(&a));
    float2 fb = __bfloat1622float2(*reinterpret_cast<__nv_bfloat162*>(&b));
    return packbf2(w0 * fa.x + w1 * fb.x, w0 * fa.y + w1 * fb.y);
}
#define CP_ASYNC16(dst, src) \
    asm volatile("cp.async.cg.shared.global [%0], [%1], 16;" :: "r"(dst), "l"(src))
#define CP_COMMIT() asm volatile("cp.async.commit_group;")
#define CP_WAIT0()  asm volatile("cp.async.wait_group 0;" ::: "memory")

// ---------------- SMEM layout ----------------
#define S0     0
#define S1     TILE_B
#define S2     (2 * TILE_B)
#define SM_RED (3 * TILE_B)              // 8 floats
#define SM_LN  (SM_RED + 32)
#define SMEM_FUSED (SM_RED + 64)         // 104512
#define SM_RED_L0  (2 * TILE_B)
#define SMEM_L0    (SM_RED_L0 + 64)      // 69696

// ---------------------------------------------------------------------------
// C = A(128x128) @ B(128x128) from SMEM tiles (row-major, pitch 136),
// Frobenius-normalize, write bf16 row-major to outp (generic ptr, pitch bytes).
// 256 threads. Caller must __syncthreads() before calling. No trailing sync.
// ---------------------------------------------------------------------------
__device__ __forceinline__ void mma_core(
    uint32_t a_base, uint32_t b_base,
    char* __restrict__ outp, uint32_t out_pitch,
    float* red, float* __restrict__ ln_slot)
{
    const int tid  = threadIdx.x;
    const int lane = tid & 31, wid = tid >> 5;
    const int wr = wid >> 2, wc = wid & 3;

    float acc[4][4][4];
    #pragma unroll
    for (int i = 0; i < 4; ++i)
        #pragma unroll
        for (int j = 0; j < 4; ++j)
            #pragma unroll
            for (int v = 0; v < 4; ++v) acc[i][j][v] = 0.f;

    const int l15 = lane & 15, lhi = (lane >> 4) << 3;

    #pragma unroll
    for (int kc = 0; kc < 8; ++kc) {
        const int k0 = kc * 16;
        uint32_t a[4][4], bf[2][4];
        #pragma unroll
        for (int mi = 0; mi < 4; ++mi) {
            int row = wr * 64 + mi * 16 + l15;
            ldm_x4(a[mi], a_base + (uint32_t)(row * PITCH + k0 + lhi) * 2);
        }
        #pragma unroll
        for (int nb = 0; nb < 2; ++nb) {
            int krow = k0 + l15;
            int ncol = wc * 32 + nb * 16 + lhi;
            ldm_x4_t(bf[nb], b_base + (uint32_t)(krow * PITCH + ncol) * 2);
        }
        #pragma unroll
        for (int mi = 0; mi < 4; ++mi)
            #pragma unroll
            for (int nj = 0; nj < 4; ++nj)
                mma16816(acc[mi][nj], a[mi], &bf[nj >> 1][(nj & 1) * 2]);
    }

    float s = 0.f;
    #pragma unroll
    for (int i = 0; i < 4; ++i)
        #pragma unroll
        for (int j = 0; j < 4; ++j)
            #pragma unroll
            for (int v = 0; v < 4; ++v) s = fmaf(acc[i][j][v], acc[i][j][v], s);
    #pragma unroll
    for (int o = 16; o > 0; o >>= 1) s += __shfl_xor_sync(0xffffffffu, s, o);

    if (lane == 0) red[wid] = s;
    __syncthreads();                       // also: all ldmatrix reads done
    if (tid == 0) {
        float t = 0.f;
        #pragma unroll
        for (int w = 0; w < 8; ++w) t += red[w];
        float nrm = fmaxf(sqrtf(t), 1e-12f);
        *ln_slot = logf(nrm);
        red[0] = 1.f / nrm;
    }
    __syncthreads();
    const float inv = red[0];

    const int g = lane >> 2, q = lane & 3;
    #pragma unroll
    for (int mi = 0; mi < 4; ++mi) {
        int r0 = wr * 64 + mi * 16 + g;
        #pragma unroll
        for (int nj = 0; nj < 4; ++nj) {
            int c = wc * 32 + nj * 8 + q * 2;
            *(uint32_t*)(outp + (size_t)r0 * out_pitch + c * 2) =
                packbf2(acc[mi][nj][0] * inv, acc[mi][nj][1] * inv);
            *(uint32_t*)(outp + (size_t)(r0 + 8) * out_pitch + c * 2) =
                packbf2(acc[mi][nj][2] * inv, acc[mi][nj][3] * inv);
        }
    }
}

// Global row-major bf16 [128][128] -> padded SMEM tile via cp.async.
__device__ __forceinline__ void load_tile_ca(uint32_t dst_base,
                                             const __nv_bfloat16* src, int tid) {
    #pragma unroll
    for (int it = 0; it < 8; ++it) {
        int idx = it * 256 + tid;
        int row = idx >> 4, col = (idx & 15) << 3;
        CP_ASYNC16(dst_base + (uint32_t)(row * PITCH + col) * 2,
                   src + (size_t)row * HD + col);
    }
}

// ---------------- pre-pass: fp32 -> bf16 ----------------
__global__ void __launch_bounds__(256) conv_cores(
    const float* __restrict__ cores, const float* __restrict__ core0)
{
    if (blockIdx.x < 8160) {
        size_t i = (size_t)blockIdx.x * 256 + threadIdx.x;
        float4 v = ((const float4*)cores)[i];
        uint2 o; o.x = packbf2(v.x, v.y); o.y = packbf2(v.z, v.w);
        ((uint2*)g_cores_bf)[i] = o;
    } else if (threadIdx.x < 64) {
        float4 v = ((const float4*)core0)[threadIdx.x];
        uint2 o; o.x = packbf2(v.x, v.y); o.y = packbf2(v.z, v.w);
        ((uint2*)g_core0_bf)[threadIdx.x] = o;
    }
}

// ---------------- Level 0: blend bf16 items + 1 matmul ----------------
__global__ void __launch_bounds__(256) mps_level0(const float* __restrict__ x)
{
    extern __shared__ char sm[];
    const int j = blockIdx.x, b = blockIdx.y, tid = threadIdx.x;
    uint32_t smb = smem_u32(sm);

    const int kA = 2 * j, kB = 2 * j + 1;
    const float xA = x[b * 256 + kA], xB = x[b * 256 + kB];
    const float wA0 = 1.f - xA, wA1 = xA;
    const float wB0 = 1.f - xB, wB1 = xB;
    const __nv_bfloat16* cA = g_cores_bf + (size_t)(kA - 1) * (HD * 2 * HD);
    const __nv_bfloat16* cB = g_cores_bf + (size_t)(kB - 1) * (HD * 2 * HD);

    #pragma unroll
    for (int it = 0; it < 8; ++it) {
        int idx = it * 256 + tid;
        int l = idx >> 4, h = (idx & 15) << 3;
        uint4 vA;
        if (kA == 0) {
            if (l == 0) {
                uint4 p0 = *(const uint4*)(g_core0_bf + h);
                uint4 p1 = *(const uint4*)(g_core0_bf + HD + h);
                vA.x = blend2(p0.x, p1.x, wA0, wA1);
                vA.y = blend2(p0.y, p1.y, wA0, wA1);
                vA.z = blend2(p0.z, p1.z, wA0, wA1);
                vA.w = blend2(p0.w, p1.w, wA0, wA1);
            } else {
                vA = make_uint4(0, 0, 0, 0);
            }
        } else {
            const __nv_bfloat16* p = cA + ((size_t)l * 2) * HD + h;
            uint4 p0 = *(const uint4*)(p);
            uint4 p1 = *(const uint4*)(p + HD);
            vA.x = blend2(p0.x, p1.x, wA0, wA1);
            vA.y = blend2(p0.y, p1.y, wA0, wA1);
            vA.z = blend2(p0.z, p1.z, wA0, wA1);
            vA.w = blend2(p0.w, p1.w, wA0, wA1);
        }
        *(uint4*)(sm + S0 + (size_t)(l * PITCH + h) * 2) = vA;

        const __nv_bfloat16* q = cB + ((size_t)l * 2) * HD + h;
        uint4 q0 = *(const uint4*)(q);
        uint4 q1 = *(const uint4*)(q + HD);
        uint4 vB;
        vB.x = blend2(q0.x, q1.x, wB0, wB1);
        vB.y = blend2(q0.y, q1.y, wB0, wB1);
        vB.z = blend2(q0.z, q1.z, wB0, wB1);
        vB.w = blend2(q0.w, q1.w, wB0, wB1);
        *(uint4*)(sm + S1 + (size_t)(l * PITCH + h) * 2) = vB;
    }
    __syncthreads();

    __nv_bfloat16* outp = g_bufA + ((size_t)b * 128 + j) * (HD * HD);
    mma_core(smb + S0, smb + S1, (char*)outp, 256,
             (float*)(sm + SM_RED_L0), &g_lognorm[b * 256 + j]);
}

// ---------------- Fused 2-level tree: 4 matrices -> 1 ----------------
template <bool A2B>
__global__ void __launch_bounds__(256) mps_fused(int lbase_lo, int lbase_hi)
{
    extern __shared__ char sm[];
    const int j = blockIdx.x, b = blockIdx.y, pairs = gridDim.x;
    const int tid = threadIdx.x;
    uint32_t smb = smem_u32(sm);
    float* red = (float*)(sm + SM_RED);

    const __nv_bfloat16* in  = A2B ? g_bufA : g_bufB;
    __nv_bfloat16*       out = A2B ? g_bufB : g_bufA;
    const __nv_bfloat16* M = in + ((size_t)b * pairs * 4 + 4 * j) * (HD * HD);

    // E = norm(M0*M1) -> S2
    load_tile_ca(smb + S0, M,            tid);
    load_tile_ca(smb + S1, M + HD * HD,  tid);
    CP_COMMIT(); CP_WAIT0();
    __syncthreads();
    mma_core(smb + S0, smb + S1, sm + S2, PITCH * 2,
             red, &g_lognorm[b * 256 + lbase_lo + 2 * j]);
    __syncthreads();

    // F = norm(M2*M3) -> S0 (safe: all reads of S0 precede mma_core's barrier)
    load_tile_ca(smb + S0, M + 2 * HD * HD, tid);
    load_tile_ca(smb + S1, M + 3 * HD * HD, tid);
    CP_COMMIT(); CP_WAIT0();
    __syncthreads();
    mma_core(smb + S0, smb + S1, sm + S0, PITCH * 2,
             red, &g_lognorm[b * 256 + lbase_lo + 2 * j + 1]);
    __syncthreads();

    // G = norm(E*F) -> global
    __nv_bfloat16* outp = out + ((size_t)b * pairs + j) * (HD * HD);
    mma_core(smb + S2, smb + S0, (char*)outp, 256,
             red, &g_lognorm[b * 256 + lbase_hi + j]);
}

// ---------------- Last level + logits ----------------
__global__ void __launch_bounds__(256) mps_last(
    const float* __restrict__ classifier, float* __restrict__ out)
{
    extern __shared__ char sm[];
    const int b = blockIdx.x, tid = threadIdx.x;
    const int lane = tid & 31, wid = tid >> 5;
    uint32_t smb = smem_u32(sm);
    float* red = (float*)(sm + SM_RED);
    float* lnp = (float*)(sm + SM_LN);

    const __nv_bfloat16* M = g_bufB + (size_t)b * 2 * (HD * HD);
    load_tile_ca(smb + S0, M,           tid);
    load_tile_ca(smb + S1, M + HD * HD, tid);
    CP_COMMIT(); CP_WAIT0();
    __syncthreads();
    mma_core(smb + S0, smb + S1, sm + S2, PITCH * 2, red, lnp);
    __syncthreads();

    // sum of 254 prior log-norms + the one just computed (in lnp)
    float ls = 0.f;
    for (int i = tid; i < 254; i += 256) ls += g_lognorm[b * 256 + i];
    #pragma unroll
    for (int o = 16; o > 0; o >>= 1) ls += __shfl_xor_sync(0xffffffffu, ls, o);
    if (lane == 0) red[wid] = ls;
    __syncthreads();
    if (tid == 0) {
        float t = lnp[0];
        #pragma unroll
        for (int w = 0; w < 8; ++w) t += red[w];
        red[0] = t;
    }
    __syncthreads();
    float lsum = red[0];

    if (tid < OUTC) {
        const __nv_bfloat16* row0 = (const __nv_bfloat16*)(sm + S2); // row 0, pitch irrelevant
        float s = 0.f;
        #pragma unroll
        for (int h = 0; h < HD; ++h)
            s = fmaf(__bfloat162float(row0[h]), classifier[tid * HD + h], s);
        out[b * OUTC + tid] = s + lsum;
    }
}

extern "C" void kernel_launch(void* const* d_in, const int* in_sizes, int n_in,
                              void* d_out, int out_size)
{
    (void)in_sizes; (void)n_in; (void)out_size;
    const float* x          = (const float*)d_in[0];
    const float* core0      = (const float*)d_in[1];
    const float* cores      = (const float*)d_in[2];
    const float* classifier = (const float*)d_in[3];
    float*       out        = (float*)d_out;

    cudaFuncSetAttribute(mps_level0, cudaFuncAttributeMaxDynamicSharedMemorySize, SMEM_L0);
    cudaFuncSetAttribute(mps_fused<true>,  cudaFuncAttributeMaxDynamicSharedMemorySize, SMEM_FUSED);
    cudaFuncSetAttribute(mps_fused<false>, cudaFuncAttributeMaxDynamicSharedMemorySize, SMEM_FUSED);
    cudaFuncSetAttribute(mps_last, cudaFuncAttributeMaxDynamicSharedMemorySize, SMEM_FUSED);

    conv_cores<<<8161, 256>>>(cores, core0);
    mps_level0<<<dim3(128, BATCH), 256, SMEM_L0>>>(x);             // 256 items -> 128 (bufA), slots 0..127
    mps_fused<true ><<<dim3(32, BATCH), 256, SMEM_FUSED>>>(128, 192); // 128 -> 32 (bufB)
    mps_fused<false><<<dim3( 8, BATCH), 256, SMEM_FUSED>>>(224, 240); // 32 -> 8  (bufA)
    mps_fused<true ><<<dim3( 2, BATCH), 256, SMEM_FUSED>>>(248, 252); // 8  -> 2  (bufB)
    mps_last<<<BATCH, 256, SMEM_FUSED>>>(classifier, out);            // 2 -> logits
}

// round 5
// speedup vs baseline: 5.1416x; 1.2350x over previous
#include <cuda_runtime.h>
#include <cuda_bf16.h>
#include <math.h>
#include <stdint.h>

#define BATCH  64
#define HD     128
#define OUTC   10

#define PITCHV 136      // V row pitch, bf16 elems
#define PITCHC 264      // chain-matrix SMEM row pitch, bf16 elems
#define CB_BYTES (128 * PITCHC * 2)            // 67584 per buffer
#define V_OFF    (2 * CB_BYTES)                // 135168
#define XS_OFF   (V_OFF + 16 * PITCHV * 2)     // 139520
#define LG_OFF   (XS_OFF + 16 * 256 * 4)       // 155904
#define RI_OFF   (LG_OFF + 64)
#define LT_OFF   (RI_OFF + 64)
#define SMEM_MAIN (LT_OFF + 64)                // 156096

// chain matrices: g_chain[m][l][2h+d] = cores[m][l][d][h]   (bf16, 16.7 MB)
__device__ __nv_bfloat16 g_chain[(size_t)255 * 128 * 256];

// ---------------- helpers ----------------
__device__ __forceinline__ uint32_t smem_u32(const void* p) {
    uint32_t a;
    asm("{ .reg .u64 t; cvta.to.shared.u64 t, %1; cvt.u32.u64 %0, t; }" : "=r"(a) : "l"(p));
    return a;
}
__device__ __forceinline__ void ldm_x4(uint32_t* r, uint32_t addr) {
    asm volatile("ldmatrix.sync.aligned.m8n8.x4.shared.b16 {%0,%1,%2,%3}, [%4];"
                 : "=r"(r[0]), "=r"(r[1]), "=r"(r[2]), "=r"(r[3]) : "r"(addr));
}
__device__ __forceinline__ void ldm_x4_t(uint32_t* r, uint32_t addr) {
    asm volatile("ldmatrix.sync.aligned.m8n8.x4.trans.shared.b16 {%0,%1,%2,%3}, [%4];"
                 : "=r"(r[0]), "=r"(r[1]), "=r"(r[2]), "=r"(r[3]) : "r"(addr));
}
__device__ __forceinline__ void mma16816(float* c, const uint32_t* a, const uint32_t* b) {
    asm volatile(
        "mma.sync.aligned.m16n8k16.row.col.f32.bf16.bf16.f32 "
        "{%0,%1,%2,%3}, {%4,%5,%6,%7}, {%8,%9}, {%0,%1,%2,%3};"
        : "+f"(c[0]), "+f"(c[1]), "+f"(c[2]), "+f"(c[3])
        : "r"(a[0]), "r"(a[1]), "r"(a[2]), "r"(a[3]), "r"(b[0]), "r"(b[1]));
}
__device__ __forceinline__ uint32_t packbf2(float a, float b) {
    __nv_bfloat162 t = __floats2bfloat162_rn(a, b);
    return *reinterpret_cast<uint32_t*>(&t);
}
#define CP_ASYNC16(dst, src) \
    asm volatile("cp.async.cg.shared.global [%0], [%1], 16;" :: "r"(dst), "l"(src))
#define CP_COMMIT() asm volatile("cp.async.commit_group;")
#define CP_WAIT0()  asm volatile("cp.async.wait_group 0;" ::: "memory")
#define CP_WAIT1()  asm volatile("cp.async.wait_group 1;" ::: "memory")

// global bf16 [128][256] -> SMEM pitched (PITCHC) via cp.async
__device__ __forceinline__ void prefetch_mat(uint32_t dst, const __nv_bfloat16* src, int tid) {
    #pragma unroll
    for (int it = 0; it < 16; ++it) {
        int c = it * 256 + tid;            // 4096 16B chunks
        int row = c >> 5, part = c & 31;
        CP_ASYNC16(dst + (uint32_t)(row * (PITCHC * 2) + part * 16),
                   (const char*)src + (size_t)row * 512 + part * 16);
    }
}

// ---------------- pre-pass: cores fp32 (n,l,d,h) -> g_chain bf16 (n,l,2h+d) ----
__global__ void __launch_bounds__(256) conv_chain(const float* __restrict__ cores)
{
    int idx = blockIdx.x * 256 + threadIdx.x;   // (n*128+l)*128 + h, total 255*128*128
    int h = idx & 127;
    int nl = idx >> 7;                          // n*128 + l
    const float* p = cores + ((size_t)nl * 2) * 128 + h;
    float d0 = p[0], d1 = p[128];
    ((uint32_t*)g_chain)[(size_t)nl * 128 + h] = packbf2(d0, d1);
}

// ---------------- main: batched vector chain ----------------
__global__ void __launch_bounds__(256) mps_chain(
    const float* __restrict__ x, const float* __restrict__ core0,
    const float* __restrict__ classifier, float* __restrict__ out)
{
    extern __shared__ char sm[];
    uint32_t smb = smem_u32(sm);
    const int tid = threadIdx.x, lane = tid & 31, wc = tid >> 5;  // warp = col-group
    const int b0 = blockIdx.x * 16;

    float* XS   = (float*)(sm + XS_OFF);    // [16][256] x values
    float* LOGS = (float*)(sm + LG_OFF);    // accumulated log norms per row
    float* RINV = (float*)(sm + RI_OFF);
    float* LTOT = (float*)(sm + LT_OFF);

    // load x slice
    #pragma unroll
    for (int it = 0; it < 16; ++it) {
        int idx = it * 256 + tid;           // bb*256 + n
        XS[idx] = x[(size_t)(b0 + (idx >> 8)) * 256 + (idx & 255)];
    }
    if (tid < 16) LOGS[tid] = 0.f;
    __syncthreads();

    // init V[bb][h] = (1-x0)*core0[0,h] + x0*core0[1,h]
    #pragma unroll
    for (int it = 0; it < 8; ++it) {
        int idx = it * 256 + tid;
        int bb = idx >> 7, h = idx & 127;
        float xv = XS[bb * 256];
        float v = (1.f - xv) * core0[h] + xv * core0[HD + h];
        *(__nv_bfloat16*)(sm + V_OFF + bb * (PITCHV * 2) + h * 2) = __float2bfloat16(v);
    }

    prefetch_mat(smb + 0, g_chain, tid); CP_COMMIT();

    const int l15 = lane & 15, lhi = (lane >> 4) << 3;
    const int r = lane >> 2, q = lane & 3;

    for (int m = 0; m < 255; ++m) {
        const uint32_t cb = smb + ((m & 1) ? CB_BYTES : 0);
        if (m < 254) {
            prefetch_mat(smb + (((m + 1) & 1) ? CB_BYTES : 0),
                         g_chain + (size_t)(m + 1) * 32768, tid);
            CP_COMMIT(); CP_WAIT1();
        } else {
            CP_WAIT0();
        }
        __syncthreads();   // bar1: prev V writes + current buffer visible

        // A fragments: V 16x128, all k upfront
        uint32_t A[8][4];
        #pragma unroll
        for (int kc = 0; kc < 8; ++kc)
            ldm_x4(A[kc], smb + V_OFF + (uint32_t)(l15 * PITCHV + kc * 16 + lhi) * 2);

        float acc[4][4];
        #pragma unroll
        for (int i = 0; i < 4; ++i)
            #pragma unroll
            for (int j = 0; j < 4; ++j) acc[i][j] = 0.f;

        #pragma unroll
        for (int kc = 0; kc < 8; ++kc) {
            #pragma unroll
            for (int nb = 0; nb < 2; ++nb) {
                uint32_t bf[4];
                ldm_x4_t(bf, cb + (uint32_t)((kc * 16 + l15) * PITCHC
                                             + wc * 32 + nb * 16 + lhi) * 2);
                mma16816(acc[nb * 2 + 0], A[kc], bf);
                mma16816(acc[nb * 2 + 1], A[kc], bf + 2);
            }
        }
        __syncthreads();   // bar2: all A/B reads done -> safe to overwrite V

        // combine: V_new[b,h] = (1-x)*U + x*W  (U,W adjacent in lane's acc pair)
        const float xa = XS[r * 256 + m + 1];
        const float xb = XS[(r + 8) * 256 + m + 1];
        #pragma unroll
        for (int nj = 0; nj < 4; ++nj) {
            int h = wc * 16 + nj * 4 + q;
            float v0 = fmaf(xa, acc[nj][1], (1.f - xa) * acc[nj][0]);
            float v1 = fmaf(xb, acc[nj][3], (1.f - xb) * acc[nj][2]);
            *(__nv_bfloat16*)(sm + V_OFF + r * (PITCHV * 2) + h * 2) = __float2bfloat16(v0);
            *(__nv_bfloat16*)(sm + V_OFF + (r + 8) * (PITCHV * 2) + h * 2) = __float2bfloat16(v1);
        }

        // periodic renormalization (every 16 sites)
        if (((m + 1) & 15) == 0 && m < 254) {
            __syncthreads();
            int bb = tid >> 4, seg = tid & 15;
            __nv_bfloat16* vr = (__nv_bfloat16*)(sm + V_OFF + bb * (PITCHV * 2));
            float s = 0.f;
            #pragma unroll
            for (int j = 0; j < 8; ++j) {
                float f = __bfloat162float(vr[seg * 8 + j]);
                s = fmaf(f, f, s);
            }
            #pragma unroll
            for (int o = 8; o > 0; o >>= 1) s += __shfl_xor_sync(0xffffffffu, s, o);
            if (seg == 0) {
                float nrm = fmaxf(sqrtf(s), 1e-30f);
                LOGS[bb] += logf(nrm);
                RINV[bb] = 1.f / nrm;
            }
            __syncthreads();
            float ri = RINV[bb];
            #pragma unroll
            for (int j = 0; j < 8; ++j)
                vr[seg * 8 + j] = __float2bfloat16(__bfloat162float(vr[seg * 8 + j]) * ri);
        }
    }
    __syncthreads();

    // final norm + total log
    {
        int bb = tid >> 4, seg = tid & 15;
        const __nv_bfloat16* vr = (const __nv_bfloat16*)(sm + V_OFF + bb * (PITCHV * 2));
        float s = 0.f;
        #pragma unroll
        for (int j = 0; j < 8; ++j) {
            float f = __bfloat162float(vr[seg * 8 + j]);
            s = fmaf(f, f, s);
        }
        #pragma unroll
        for (int o = 8; o > 0; o >>= 1) s += __shfl_xor_sync(0xffffffffu, s, o);
        if (seg == 0) {
            float nrm = fmaxf(sqrtf(s), 1e-30f);
            RINV[bb] = 1.f / nrm;
            LTOT[bb] = LOGS[bb] + logf(nrm);
        }
    }
    __syncthreads();

    // logits[b0+bb, o] = <v_hat, classifier[o]> + log_total
    if (tid < 16 * OUTC) {
        int bb = tid / OUTC, o = tid % OUTC;
        const __nv_bfloat16* vr = (const __nv_bfloat16*)(sm + V_OFF + bb * (PITCHV * 2));
        float s = 0.f;
        #pragma unroll
        for (int h = 0; h < HD; ++h)
            s = fmaf(__bfloat162float(vr[h]), classifier[o * HD + h], s);
        out[(size_t)(b0 + bb) * OUTC + o] = s * RINV[bb] + LTOT[bb];
    }
}

extern "C" void kernel_launch(void* const* d_in, const int* in_sizes, int n_in,
                              void* d_out, int out_size)
{
    (void)in_sizes; (void)n_in; (void)out_size;
    const float* x          = (const float*)d_in[0];
    const float* core0      = (const float*)d_in[1];
    const float* cores      = (const float*)d_in[2];
    const float* classifier = (const float*)d_in[3];
    float*       out        = (float*)d_out;

    cudaFuncSetAttribute(mps_chain, cudaFuncAttributeMaxDynamicSharedMemorySize, SMEM_MAIN);

    conv_chain<<<16320, 256>>>(cores);                     // 255*128*128 threads
    mps_chain<<<4, 256, SMEM_MAIN>>>(x, core0, classifier, out);
}